// round 1
// baseline (speedup 1.0000x reference)
#include <cuda_runtime.h>
#include <math.h>

#define N_INST 256
#define BATCH  128
#define IN_DIM 1024
#define L_DIM  512

#define BK 32
#define BL 32
#define NLT (L_DIM / BL)     // 16 l-tiles
#define VS_STRIDE 36         // padded [l][k] stride to avoid STS conflicts

// Scratch for scores (allocation-free rule: __device__ global)
__device__ float g_scores[N_INST * BATCH];

// Packed fp32x2 FMA (sm_10x FFMA2): d.lo += a.lo*b.lo ; d.hi += a.hi*b.hi
__device__ __forceinline__ void fma2(unsigned long long &d,
                                     unsigned long long a,
                                     unsigned long long b) {
    asm volatile("fma.rn.f32x2 %0, %1, %2, %0;" : "+l"(d) : "l"(a), "l"(b));
}

__device__ __forceinline__ float pairsum(unsigned long long t) {
    float lo = __uint_as_float((unsigned int)(t & 0xffffffffULL));
    float hi = __uint_as_float((unsigned int)(t >> 32));
    return lo + hi;
}

// One block per instance n. Computes scores[n][0..127] =
// (tanh(X_n V) * sigmoid(X_n U)) @ w, fully fused, fp32.
__global__ void __launch_bounds__(256, 1)
gemm_score_kernel(const float* __restrict__ x,
                  const float* __restrict__ v,
                  const float* __restrict__ u,
                  const float* __restrict__ w)
{
    const int n   = blockIdx.x;
    const int tid = threadIdx.x;
    const int colgrp = tid & 15;   // 16 column groups x 2 cols = 32 cols (BL)
    const int rowgrp = tid >> 4;   // 16 row groups    x 8 rows = 128 rows (BATCH)
    const int row0 = rowgrp * 8;
    const int col0 = colgrp * 2;

    __shared__ float xs[BATCH * BK];          // [b][k], k contiguous (natural pairs)
    __shared__ float vs[BL * VS_STRIDE];      // [l][k], transposed on load
    __shared__ float us[BL * VS_STRIDE];
    __shared__ float red[16 * BATCH];         // deterministic cross-column reduction

    const float* xn = x + (size_t)n * (BATCH * IN_DIM);

    float sc[8];
#pragma unroll
    for (int i = 0; i < 8; i++) sc[i] = 0.0f;

    const int dk = tid >> 3;        // 0..31  (k index for v/u tile load)
    const int dl = (tid & 7) * 4;   // 0..28  (l index, float4)

    for (int lt = 0; lt < NLT; lt++) {
        const int l0 = lt * BL;

        // Packed accumulators: lo half accumulates even-k partial sum, hi half odd-k.
        unsigned long long aV[8][2], aU[8][2];
#pragma unroll
        for (int i = 0; i < 8; i++) {
            aV[i][0] = 0ULL; aV[i][1] = 0ULL;
            aU[i][0] = 0ULL; aU[i][1] = 0ULL;
        }

        for (int k0 = 0; k0 < IN_DIM; k0 += BK) {
            // X tile [128 b][32 k]: 1024 float4, 4 per thread, conflict-free STS.128
#pragma unroll
            for (int i = 0; i < 4; i++) {
                int idx = tid + i * 256;
                int b  = idx >> 3;
                int kk = (idx & 7) << 2;
                float4 val = *(const float4*)(xn + b * IN_DIM + k0 + kk);
                *(float4*)(xs + b * BK + kk) = val;
            }
            // V/U tiles [32 k][32 l] -> transposed to [l][k] (pad 36)
            {
                float4 vv = *(const float4*)(v + (size_t)(k0 + dk) * L_DIM + l0 + dl);
                vs[(dl + 0) * VS_STRIDE + dk] = vv.x;
                vs[(dl + 1) * VS_STRIDE + dk] = vv.y;
                vs[(dl + 2) * VS_STRIDE + dk] = vv.z;
                vs[(dl + 3) * VS_STRIDE + dk] = vv.w;
                float4 uu = *(const float4*)(u + (size_t)(k0 + dk) * L_DIM + l0 + dl);
                us[(dl + 0) * VS_STRIDE + dk] = uu.x;
                us[(dl + 1) * VS_STRIDE + dk] = uu.y;
                us[(dl + 2) * VS_STRIDE + dk] = uu.z;
                us[(dl + 3) * VS_STRIDE + dk] = uu.w;
            }
            __syncthreads();

            // 32 k's in steps of 4: LDS.128 yields two k-adjacent f32x2 pairs directly.
#pragma unroll
            for (int kk = 0; kk < BK; kk += 4) {
                ulonglong2 vq0 = *(const ulonglong2*)(vs + (col0 + 0) * VS_STRIDE + kk);
                ulonglong2 vq1 = *(const ulonglong2*)(vs + (col0 + 1) * VS_STRIDE + kk);
                ulonglong2 uq0 = *(const ulonglong2*)(us + (col0 + 0) * VS_STRIDE + kk);
                ulonglong2 uq1 = *(const ulonglong2*)(us + (col0 + 1) * VS_STRIDE + kk);
#pragma unroll
                for (int i = 0; i < 8; i++) {
                    ulonglong2 xq = *(const ulonglong2*)(xs + (row0 + i) * BK + kk);
                    fma2(aV[i][0], xq.x, vq0.x);
                    fma2(aV[i][0], xq.y, vq0.y);
                    fma2(aV[i][1], xq.x, vq1.x);
                    fma2(aV[i][1], xq.y, vq1.y);
                    fma2(aU[i][0], xq.x, uq0.x);
                    fma2(aU[i][0], xq.y, uq0.y);
                    fma2(aU[i][1], xq.x, uq1.x);
                    fma2(aU[i][1], xq.y, uq1.y);
                }
            }
            __syncthreads();
        }

        // Epilogue for this l-tile: gate + weight, accumulate per-row score.
        const float w0 = w[l0 + col0 + 0];
        const float w1 = w[l0 + col0 + 1];
#pragma unroll
        for (int i = 0; i < 8; i++) {
            float a0 = pairsum(aV[i][0]);
            float a1 = pairsum(aV[i][1]);
            float g0 = pairsum(aU[i][0]);
            float g1 = pairsum(aU[i][1]);
            float h0 = tanhf(a0) * (1.0f / (1.0f + expf(-g0)));
            float h1 = tanhf(a1) * (1.0f / (1.0f + expf(-g1)));
            sc[i] += h0 * w0 + h1 * w1;
        }
    }

    // Deterministic reduction across the 16 column groups.
#pragma unroll
    for (int i = 0; i < 8; i++)
        red[colgrp * BATCH + row0 + i] = sc[i];
    __syncthreads();
    if (tid < BATCH) {
        float s = 0.0f;
#pragma unroll
        for (int j = 0; j < 16; j++) s += red[j * BATCH + tid];
        g_scores[n * BATCH + tid] = s;
    }
}

// Softmax over the instance axis (n = 0..255) for each batch column b.
__global__ void softmax_kernel(float* __restrict__ out)
{
    const int b   = blockIdx.x;    // 0..127
    const int tid = threadIdx.x;   // 0..255 == n
    __shared__ float sh[256];

    float s = g_scores[tid * BATCH + b];
    sh[tid] = s;
    __syncthreads();
#pragma unroll
    for (int off = 128; off > 0; off >>= 1) {
        if (tid < off) sh[tid] = fmaxf(sh[tid], sh[tid + off]);
        __syncthreads();
    }
    float m = sh[0];
    __syncthreads();

    float e = expf(s - m);
    sh[tid] = e;
    __syncthreads();
#pragma unroll
    for (int off = 128; off > 0; off >>= 1) {
        if (tid < off) sh[tid] += sh[tid + off];
        __syncthreads();
    }
    float denom = sh[0];

    out[tid * BATCH + b] = e / denom;
}

extern "C" void kernel_launch(void* const* d_in, const int* in_sizes, int n_in,
                              void* d_out, int out_size)
{
    const float* x = (const float*)d_in[0];
    const float* v = (const float*)d_in[1];
    const float* u = (const float*)d_in[2];
    const float* w = (const float*)d_in[3];
    float* out = (float*)d_out;

    gemm_score_kernel<<<N_INST, 256>>>(x, v, u, w);
    softmax_kernel<<<BATCH, 256>>>(out);
}

// round 3
// speedup vs baseline: 3.9806x; 3.9806x over previous
#include <cuda_runtime.h>
#include <cuda_bf16.h>
#include <cuda_fp16.h>
#include <cstdint>
#include <math.h>

#define N_INST 256
#define BATCH  128
#define IN_DIM 1024
#define L_DIM  512

// ---------------- device scratch (allocation-free rule) ----------------
__device__ __align__(256) __nv_bfloat16 g_xh[(size_t)N_INST * BATCH * IN_DIM]; // 64MB
__device__ __align__(256) __nv_bfloat16 g_xl[(size_t)N_INST * BATCH * IN_DIM]; // 64MB
__device__ __align__(256) __nv_bfloat16 g_vh[L_DIM * IN_DIM]; // [l][k] transposed
__device__ __align__(256) __nv_bfloat16 g_vl[L_DIM * IN_DIM];
__device__ __align__(256) __nv_bfloat16 g_uh[L_DIM * IN_DIM];
__device__ __align__(256) __nv_bfloat16 g_ul[L_DIM * IN_DIM];
__device__ float g_scores[N_INST * BATCH];

// ---------------- helpers ----------------
__device__ __forceinline__ uint32_t smem_u32(const void* p) {
    uint32_t a;
    asm("{ .reg .u64 t; cvta.to.shared.u64 t, %1; cvt.u32.u64 %0, t; }" : "=r"(a) : "l"(p));
    return a;
}
// 64B-row swizzle: XOR row bits [8:7] into 16B-chunk bits [5:4]
#define SWZ64(off) ((off) ^ (((off) >> 3) & 0x30))

#define CP16(dst, src) \
    asm volatile("cp.async.cg.shared.global [%0], [%1], 16;" :: "r"(dst), "l"(src))
#define CP_COMMIT() asm volatile("cp.async.commit_group;" ::: "memory")
#define CP_WAIT(n)  asm volatile("cp.async.wait_group %0;" :: "n"(n) : "memory")

__device__ __forceinline__ void ldsm4(uint32_t* r, uint32_t addr) {
    asm volatile("ldmatrix.sync.aligned.m8n8.x4.shared.b16 {%0,%1,%2,%3}, [%4];"
                 : "=r"(r[0]), "=r"(r[1]), "=r"(r[2]), "=r"(r[3]) : "r"(addr));
}
__device__ __forceinline__ void mma16816(float* c, const uint32_t* a, const uint32_t* b) {
    asm volatile("mma.sync.aligned.m16n8k16.row.col.f32.bf16.bf16.f32 "
                 "{%0,%1,%2,%3}, {%4,%5,%6,%7}, {%8,%9}, {%0,%1,%2,%3};"
                 : "+f"(c[0]), "+f"(c[1]), "+f"(c[2]), "+f"(c[3])
                 : "r"(a[0]), "r"(a[1]), "r"(a[2]), "r"(a[3]), "r"(b[0]), "r"(b[1]));
}

// ---------------- prep kernels ----------------
__global__ void prep_x_kernel(const float4* __restrict__ x4) {
    size_t i = (size_t)blockIdx.x * 256 + threadIdx.x;      // 8388608 threads
    float4 f = x4[i];
    float a[4] = {f.x, f.y, f.z, f.w};
    unsigned short hs[4], ls[4];
#pragma unroll
    for (int j = 0; j < 4; j++) {
        __nv_bfloat16 h = __float2bfloat16(a[j]);
        float hf = __bfloat162float(h);
        __nv_bfloat16 lo = __float2bfloat16(a[j] - hf);
        hs[j] = __bfloat16_as_ushort(h);
        ls[j] = __bfloat16_as_ushort(lo);
    }
    uint2 hh = make_uint2((uint32_t)hs[0] | ((uint32_t)hs[1] << 16),
                          (uint32_t)hs[2] | ((uint32_t)hs[3] << 16));
    uint2 ll = make_uint2((uint32_t)ls[0] | ((uint32_t)ls[1] << 16),
                          (uint32_t)ls[2] | ((uint32_t)ls[3] << 16));
    size_t o = i * 4;
    *(uint2*)(g_xh + o) = hh;
    *(uint2*)(g_xl + o) = ll;
}

__global__ void prep_vu_kernel(const float* __restrict__ v, const float* __restrict__ u) {
    int gid = blockIdx.x * 256 + threadIdx.x;               // 524288 threads
    int k = gid & (IN_DIM - 1);
    int l = gid >> 10;
    float fv = v[(size_t)k * L_DIM + l];
    float fu = u[(size_t)k * L_DIM + l];
    __nv_bfloat16 vh = __float2bfloat16(fv);
    __nv_bfloat16 vl = __float2bfloat16(fv - __bfloat162float(vh));
    __nv_bfloat16 uh = __float2bfloat16(fu);
    __nv_bfloat16 ul = __float2bfloat16(fu - __bfloat162float(uh));
    size_t o = (size_t)l * IN_DIM + k;
    g_vh[o] = vh; g_vl[o] = vl; g_uh[o] = uh; g_ul[o] = ul;
}

// ---------------- main fused GEMM kernel ----------------
// SMEM map (bytes):
#define SM_W      0          // 512 f32 = 2048
#define SM_RED    2048       // 256 f32 = 1024
#define SM_STASH  3072       // 128 rows x 264B (fp16, padded) = 33792 -> ends 36864
#define STASH_STRIDE 264
#define SM_TILES  36864
#define BUF_STRIDE 49152     // per buffer: A_hi 8K, A_lo 8K, B_hi 16K, B_lo 16K
#define OFF_A_HI  0
#define OFF_A_LO  8192
#define OFF_B_HI  16384
#define OFF_B_LO  32768
#define SM_TOTAL  (36864 + 2 * BUF_STRIDE)   // 135168

#define BK 32
#define NI (IN_DIM / BK)     // 32 K-iterations per chunk
#define NCHUNK 4             // l-chunks of 128 cols (V+U each)

__global__ void __launch_bounds__(512, 1)
mil_gemm_kernel(const float* __restrict__ w)
{
    extern __shared__ char smem[];
    const int n    = blockIdx.x;
    const int tid  = threadIdx.x;
    const int lane = tid & 31;
    const int wid  = tid >> 5;
    const int mw   = wid & 3;    // M band: rows mw*32..+31
    const int nw   = wid >> 2;   // N band: combined cols nw*64..+63 (nw<2: V, nw>=2: U)
    const uint32_t smem_base = smem_u32(smem);

    // w into smem
    float* ws = (float*)(smem + SM_W);
    if (tid < L_DIM) ws[tid] = w[tid];

    const __nv_bfloat16* xh = g_xh + (size_t)n * BATCH * IN_DIM;
    const __nv_bfloat16* xl = g_xl + (size_t)n * BATCH * IN_DIM;

    // ---- per-thread cp.async assignments ----
    // A: 1024 chunks (hi 0-511, lo 512-1023); each thread 2
    const __nv_bfloat16* srcA[2];
    uint32_t dstA[2];
#pragma unroll
    for (int j = 0; j < 2; j++) {
        int a_idx = j * 512 + tid;
        int hilo  = a_idx >> 9;
        int rs    = a_idx & 511;
        int arow  = rs >> 2;
        int aseg  = rs & 3;
        srcA[j] = (hilo ? xl : xh) + (size_t)arow * IN_DIM + aseg * 8;
        dstA[j] = SM_TILES + (hilo ? OFF_A_LO : OFF_A_HI) + SWZ64(arow * 64 + aseg * 16);
    }
    // B: 2048 chunks (hi 0-1023, lo 1024-2047); rows 0-127 = V, 128-255 = U
    const __nv_bfloat16* srcB[4];
    uint32_t dstB[4];
#pragma unroll
    for (int j = 0; j < 4; j++) {
        int b_idx = j * 512 + tid;
        int hilo  = b_idx >> 10;
        int rs    = b_idx & 1023;
        int brow  = rs >> 2;
        int bseg  = rs & 3;
        const __nv_bfloat16* mat;
        int lrow;
        if (brow < 128) { mat = hilo ? g_vl : g_vh; lrow = brow; }
        else            { mat = hilo ? g_ul : g_uh; lrow = brow - 128; }
        srcB[j] = mat + (size_t)lrow * IN_DIM + bseg * 8;
        dstB[j] = SM_TILES + (hilo ? OFF_B_LO : OFF_B_HI) + SWZ64(brow * 64 + bseg * 16);
    }

    float rowacc[4] = {0.f, 0.f, 0.f, 0.f};   // only U warps (nw>=2) use

    for (int lc = 0; lc < NCHUNK; lc++) {
        const int l0 = lc * 128;
        const size_t lofs = (size_t)l0 * IN_DIM;

        float acc[2][8][4];
#pragma unroll
        for (int mt = 0; mt < 2; mt++)
#pragma unroll
            for (int nt = 0; nt < 8; nt++)
#pragma unroll
                for (int r = 0; r < 4; r++) acc[mt][nt][r] = 0.f;

        // prologue: issue iter 0 into buffer 0
        {
            uint32_t bb = smem_base;
#pragma unroll
            for (int j = 0; j < 2; j++) CP16(bb + dstA[j], srcA[j]);
#pragma unroll
            for (int j = 0; j < 4; j++) CP16(bb + dstB[j], srcB[j] + lofs);
            CP_COMMIT();
        }

        for (int it = 0; it < NI; it++) {
            if (it + 1 < NI) {
                uint32_t bb = smem_base + ((it + 1) & 1) * BUF_STRIDE;
                int k0 = (it + 1) * BK;
#pragma unroll
                for (int j = 0; j < 2; j++) CP16(bb + dstA[j], srcA[j] + k0);
#pragma unroll
                for (int j = 0; j < 4; j++) CP16(bb + dstB[j], srcB[j] + lofs + k0);
                CP_COMMIT();
                CP_WAIT(1);
            } else {
                CP_WAIT(0);
            }
            __syncthreads();

            const uint32_t bb = smem_base + (it & 1) * BUF_STRIDE;
            const uint32_t aHi = bb + SM_TILES + OFF_A_HI;
            const uint32_t aLo = bb + SM_TILES + OFF_A_LO;
            const uint32_t bHi = bb + SM_TILES + OFF_B_HI;
            const uint32_t bLo = bb + SM_TILES + OFF_B_LO;

#pragma unroll
            for (int ks = 0; ks < 2; ks++) {
                // A fragments: row = mw*32 + mt*16 + (lane&15), khalf = (lane>>4)*8
                uint32_t ah[2][4], al[2][4];
                const uint32_t akoff = ks * 32 + (lane >> 4) * 16;
#pragma unroll
                for (int mt = 0; mt < 2; mt++) {
                    uint32_t rowb = (mw * 32 + mt * 16 + (lane & 15)) * 64;
                    uint32_t so = SWZ64(rowb + akoff);
                    ldsm4(ah[mt], aHi + so);
                    ldsm4(al[mt], aLo + so);
                }
                const uint32_t bkoff = ks * 32 + ((lane >> 3) & 1) * 16;
#pragma unroll
                for (int ntp = 0; ntp < 4; ntp++) {
                    // B rows: nw*64 + ntp*16 + ((lane>>4)&1)*8 + (lane&7)
                    uint32_t rowb = (nw * 64 + ntp * 16 + ((lane >> 4) & 1) * 8 + (lane & 7)) * 64;
                    uint32_t so = SWZ64(rowb + bkoff);
                    uint32_t bh[4], bl[4];
                    ldsm4(bh, bHi + so);
                    ldsm4(bl, bLo + so);
#pragma unroll
                    for (int half = 0; half < 2; half++) {
                        int nt = ntp * 2 + half;
#pragma unroll
                        for (int mt = 0; mt < 2; mt++) {
                            mma16816(acc[mt][nt], ah[mt], bh + half * 2);
                            mma16816(acc[mt][nt], ah[mt], bl + half * 2);
                            mma16816(acc[mt][nt], al[mt], bh + half * 2);
                        }
                    }
                }
            }
            __syncthreads();
        }

        // ---- epilogue for this l-chunk ----
        if (nw < 2) {
            // V warps: stash tanh as fp16
#pragma unroll
            for (int mt = 0; mt < 2; mt++)
#pragma unroll
                for (int nt = 0; nt < 8; nt++) {
                    int col = nw * 64 + nt * 8 + (lane & 3) * 2;
#pragma unroll
                    for (int half = 0; half < 2; half++) {
                        int row = mw * 32 + mt * 16 + half * 8 + (lane >> 2);
                        float h0 = tanhf(acc[mt][nt][half * 2 + 0]);
                        float h1 = tanhf(acc[mt][nt][half * 2 + 1]);
                        *(__half2*)(smem + SM_STASH + row * STASH_STRIDE + col * 2) =
                            __floats2half2_rn(h0, h1);
                    }
                }
        }
        __syncthreads();
        if (nw >= 2) {
            // U warps: gate + weight
#pragma unroll
            for (int mt = 0; mt < 2; mt++)
#pragma unroll
                for (int nt = 0; nt < 8; nt++) {
                    int vcol = (nw - 2) * 64 + nt * 8 + (lane & 3) * 2;
                    float w0 = ws[l0 + vcol + 0];
                    float w1 = ws[l0 + vcol + 1];
#pragma unroll
                    for (int half = 0; half < 2; half++) {
                        int row = mw * 32 + mt * 16 + half * 8 + (lane >> 2);
                        __half2 hh = *(const __half2*)(smem + SM_STASH +
                                                       row * STASH_STRIDE + vcol * 2);
                        float g0 = 1.0f / (1.0f + __expf(-acc[mt][nt][half * 2 + 0]));
                        float g1 = 1.0f / (1.0f + __expf(-acc[mt][nt][half * 2 + 1]));
                        rowacc[mt * 2 + half] += __low2float(hh)  * g0 * w0 +
                                                 __high2float(hh) * g1 * w1;
                    }
                }
        }
        __syncthreads();
    }

    // ---- final reduction ----
    float* red = (float*)(smem + SM_RED);
    if (nw >= 2) {
#pragma unroll
        for (int ri = 0; ri < 4; ri++) {
            float p = rowacc[ri];
            p += __shfl_xor_sync(0xffffffffu, p, 1);
            p += __shfl_xor_sync(0xffffffffu, p, 2);
            if ((lane & 3) == 0) {
                int row = mw * 32 + (ri >> 1) * 16 + (ri & 1) * 8 + (lane >> 2);
                red[(nw - 2) * 128 + row] = p;
            }
        }
    }
    __syncthreads();
    if (tid < BATCH)
        g_scores[(size_t)n * BATCH + tid] = red[tid] + red[128 + tid];
}

// ---------------- softmax over instance axis ----------------
__global__ void softmax_kernel(float* __restrict__ out)
{
    const int b   = blockIdx.x;    // 0..127
    const int tid = threadIdx.x;   // 0..255 == n
    __shared__ float sh[256];

    float s = g_scores[(size_t)tid * BATCH + b];
    sh[tid] = s;
    __syncthreads();
#pragma unroll
    for (int off = 128; off > 0; off >>= 1) {
        if (tid < off) sh[tid] = fmaxf(sh[tid], sh[tid + off]);
        __syncthreads();
    }
    float m = sh[0];
    __syncthreads();
    float e = __expf(s - m);
    sh[tid] = e;
    __syncthreads();
#pragma unroll
    for (int off = 128; off > 0; off >>= 1) {
        if (tid < off) sh[tid] += sh[tid + off];
        __syncthreads();
    }
    out[(size_t)tid * BATCH + b] = e / sh[0];
}

extern "C" void kernel_launch(void* const* d_in, const int* in_sizes, int n_in,
                              void* d_out, int out_size)
{
    const float* x = (const float*)d_in[0];
    const float* v = (const float*)d_in[1];
    const float* u = (const float*)d_in[2];
    const float* w = (const float*)d_in[3];
    float* out = (float*)d_out;

    cudaFuncSetAttribute(mil_gemm_kernel,
                         cudaFuncAttributeMaxDynamicSharedMemorySize, SM_TOTAL);

    prep_x_kernel<<<32768, 256>>>((const float4*)x);
    prep_vu_kernel<<<2048, 256>>>(v, u);
    mil_gemm_kernel<<<N_INST, 512, SM_TOTAL>>>(w);
    softmax_kernel<<<BATCH, 256>>>(out);
}

// round 4
// speedup vs baseline: 4.4506x; 1.1181x over previous
#include <cuda_runtime.h>
#include <cuda_bf16.h>
#include <cuda_fp16.h>
#include <cstdint>
#include <math.h>

#define N_INST 256
#define BATCH  128
#define IN_DIM 1024
#define L_DIM  512

// ---------------- device scratch (allocation-free rule) ----------------
__device__ __align__(256) __nv_bfloat16 g_xh[(size_t)N_INST * BATCH * IN_DIM]; // 64MB
__device__ __align__(256) __nv_bfloat16 g_xl[(size_t)N_INST * BATCH * IN_DIM]; // 64MB
__device__ __align__(256) __nv_bfloat16 g_vh[L_DIM * IN_DIM]; // [l][k] transposed
__device__ __align__(256) __nv_bfloat16 g_vl[L_DIM * IN_DIM];
__device__ __align__(256) __nv_bfloat16 g_uh[L_DIM * IN_DIM];
__device__ __align__(256) __nv_bfloat16 g_ul[L_DIM * IN_DIM];
__device__ float g_part[1024 * BATCH];   // partial scores per (instance, l-chunk)

// ---------------- helpers ----------------
__device__ __forceinline__ uint32_t smem_u32(const void* p) {
    uint32_t a;
    asm("{ .reg .u64 t; cvta.to.shared.u64 t, %1; cvt.u32.u64 %0, t; }" : "=r"(a) : "l"(p));
    return a;
}
// 64B-row swizzle: XOR row bits [8:7] into 16B-chunk bits [5:4]
#define SWZ64(off) ((off) ^ (((off) >> 3) & 0x30))

#define CP16(dst, src) \
    asm volatile("cp.async.cg.shared.global [%0], [%1], 16;" :: "r"(dst), "l"(src))
#define CP_COMMIT() asm volatile("cp.async.commit_group;" ::: "memory")
#define CP_WAIT(n)  asm volatile("cp.async.wait_group %0;" :: "n"(n) : "memory")

__device__ __forceinline__ void ldsm4(uint32_t* r, uint32_t addr) {
    asm volatile("ldmatrix.sync.aligned.m8n8.x4.shared.b16 {%0,%1,%2,%3}, [%4];"
                 : "=r"(r[0]), "=r"(r[1]), "=r"(r[2]), "=r"(r[3]) : "r"(addr));
}
__device__ __forceinline__ void mma16816(float* c, const uint32_t* a, const uint32_t* b) {
    asm volatile("mma.sync.aligned.m16n8k16.row.col.f32.bf16.bf16.f32 "
                 "{%0,%1,%2,%3}, {%4,%5,%6,%7}, {%8,%9}, {%0,%1,%2,%3};"
                 : "+f"(c[0]), "+f"(c[1]), "+f"(c[2]), "+f"(c[3])
                 : "r"(a[0]), "r"(a[1]), "r"(a[2]), "r"(a[3]), "r"(b[0]), "r"(b[1]));
}
__device__ __forceinline__ float fast_tanh(float x) {
    float t = __expf(2.0f * x);
    return (t - 1.0f) / (t + 1.0f);
}
__device__ __forceinline__ float fast_sigmoid(float x) {
    return 1.0f / (1.0f + __expf(-x));
}

// ---------------- prep kernels ----------------
__global__ void prep_x_kernel(const float4* __restrict__ x4) {
    size_t i = (size_t)blockIdx.x * 256 + threadIdx.x;      // 8388608 threads
    float4 f = x4[i];
    float a[4] = {f.x, f.y, f.z, f.w};
    unsigned short hs[4], ls[4];
#pragma unroll
    for (int j = 0; j < 4; j++) {
        __nv_bfloat16 h = __float2bfloat16(a[j]);
        float hf = __bfloat162float(h);
        __nv_bfloat16 lo = __float2bfloat16(a[j] - hf);
        hs[j] = __bfloat16_as_ushort(h);
        ls[j] = __bfloat16_as_ushort(lo);
    }
    uint2 hh = make_uint2((uint32_t)hs[0] | ((uint32_t)hs[1] << 16),
                          (uint32_t)hs[2] | ((uint32_t)hs[3] << 16));
    uint2 ll = make_uint2((uint32_t)ls[0] | ((uint32_t)ls[1] << 16),
                          (uint32_t)ls[2] | ((uint32_t)ls[3] << 16));
    size_t o = i * 4;
    *(uint2*)(g_xh + o) = hh;
    *(uint2*)(g_xl + o) = ll;
}

__global__ void prep_vu_kernel(const float* __restrict__ v, const float* __restrict__ u) {
    int gid = blockIdx.x * 256 + threadIdx.x;               // 524288 threads
    int k = gid & (IN_DIM - 1);
    int l = gid >> 10;
    float fv = v[(size_t)k * L_DIM + l];
    float fu = u[(size_t)k * L_DIM + l];
    __nv_bfloat16 vh = __float2bfloat16(fv);
    __nv_bfloat16 vl = __float2bfloat16(fv - __bfloat162float(vh));
    __nv_bfloat16 uh = __float2bfloat16(fu);
    __nv_bfloat16 ul = __float2bfloat16(fu - __bfloat162float(uh));
    size_t o = (size_t)l * IN_DIM + k;
    g_vh[o] = vh; g_vl[o] = vl; g_uh[o] = uh; g_ul[o] = ul;
}

// ---------------- main fused GEMM kernel ----------------
// One CTA per (instance n, l-chunk lc): computes the 128x128 V and U tiles for
// l-cols [lc*128, lc*128+128), gates, contracts with w -> partial score.
// SMEM map (bytes):
#define SM_W      0          // 128 f32 = 512
#define SM_RED    512        // 256 f32 = 1024
#define SM_STASH  1536       // 128 rows x 264B (fp16, padded) -> ends 35328
#define STASH_STRIDE 264
#define SM_TILES  35328      // 3 stages x 48KB
#define BUF_STRIDE 49152     // per stage: A_hi 8K, A_lo 8K, B_hi 16K, B_lo 16K
#define OFF_A_HI  0
#define OFF_A_LO  8192
#define OFF_B_HI  16384
#define OFF_B_LO  32768
#define SM_TOTAL  (SM_TILES + 3 * BUF_STRIDE)   // 182784

#define BK 32
#define NI (IN_DIM / BK)     // 32 K-iterations

__global__ void __launch_bounds__(512, 1)
mil_gemm_kernel(const float* __restrict__ w)
{
    extern __shared__ char smem[];
    const int task = blockIdx.x;       // 0..1023
    const int n    = task >> 2;
    const int lc   = task & 3;
    const int l0   = lc * 128;
    const int tid  = threadIdx.x;
    const int lane = tid & 31;
    const int wid  = tid >> 5;
    const int mw   = wid & 3;    // M band: rows mw*32..+31
    const int nw   = wid >> 2;   // N band: combined cols nw*64..+63 (nw<2: V, nw>=2: U)
    const uint32_t smem_base = smem_u32(smem);

    // w slice for this l-chunk into smem
    float* ws = (float*)(smem + SM_W);
    if (tid < 128) ws[tid] = w[l0 + tid];

    const __nv_bfloat16* xh = g_xh + (size_t)n * BATCH * IN_DIM;
    const __nv_bfloat16* xl = g_xl + (size_t)n * BATCH * IN_DIM;
    const size_t lofs = (size_t)l0 * IN_DIM;

    // ---- per-thread cp.async assignments ----
    // A: 1024 16B chunks (hi 0-511, lo 512-1023); each thread 2
    const __nv_bfloat16* srcA[2];
    uint32_t dstA[2];
#pragma unroll
    for (int j = 0; j < 2; j++) {
        int a_idx = j * 512 + tid;
        int hilo  = a_idx >> 9;
        int rs    = a_idx & 511;
        int arow  = rs >> 2;
        int aseg  = rs & 3;
        srcA[j] = (hilo ? xl : xh) + (size_t)arow * IN_DIM + aseg * 8;
        dstA[j] = SM_TILES + (hilo ? OFF_A_LO : OFF_A_HI) + SWZ64(arow * 64 + aseg * 16);
    }
    // B: 2048 chunks (hi 0-1023, lo 1024-2047); rows 0-127 = V, 128-255 = U
    const __nv_bfloat16* srcB[4];
    uint32_t dstB[4];
#pragma unroll
    for (int j = 0; j < 4; j++) {
        int b_idx = j * 512 + tid;
        int hilo  = b_idx >> 10;
        int rs    = b_idx & 1023;
        int brow  = rs >> 2;
        int bseg  = rs & 3;
        const __nv_bfloat16* mat;
        int lrow;
        if (brow < 128) { mat = hilo ? g_vl : g_vh; lrow = brow; }
        else            { mat = hilo ? g_ul : g_uh; lrow = brow - 128; }
        srcB[j] = mat + lofs + (size_t)lrow * IN_DIM + bseg * 8;
        dstB[j] = SM_TILES + (hilo ? OFF_B_LO : OFF_B_HI) + SWZ64(brow * 64 + bseg * 16);
    }

    float acc[2][8][4];
#pragma unroll
    for (int mt = 0; mt < 2; mt++)
#pragma unroll
        for (int nt = 0; nt < 8; nt++)
#pragma unroll
            for (int r = 0; r < 4; r++) acc[mt][nt][r] = 0.f;

    // ---- prologue: stages 0 and 1 ----
#pragma unroll
    for (int s = 0; s < 2; s++) {
        uint32_t bb = smem_base + s * BUF_STRIDE;
        int k0 = s * BK;
#pragma unroll
        for (int j = 0; j < 2; j++) CP16(bb + dstA[j], srcA[j] + k0);
#pragma unroll
        for (int j = 0; j < 4; j++) CP16(bb + dstB[j], srcB[j] + k0);
        CP_COMMIT();
    }

    int slot = 0, nslot = 2;
    for (int it = 0; it < NI; it++) {
        if (it + 1 < NI) { CP_WAIT(1); } else { CP_WAIT(0); }
        __syncthreads();
        if (it + 2 < NI) {
            uint32_t bb = smem_base + nslot * BUF_STRIDE;
            int k0 = (it + 2) * BK;
#pragma unroll
            for (int j = 0; j < 2; j++) CP16(bb + dstA[j], srcA[j] + k0);
#pragma unroll
            for (int j = 0; j < 4; j++) CP16(bb + dstB[j], srcB[j] + k0);
            CP_COMMIT();
            nslot = (nslot == 2) ? 0 : nslot + 1;
        }

        const uint32_t bb = smem_base + slot * BUF_STRIDE;
        slot = (slot == 2) ? 0 : slot + 1;
        const uint32_t aHi = bb + SM_TILES + OFF_A_HI;
        const uint32_t aLo = bb + SM_TILES + OFF_A_LO;
        const uint32_t bHi = bb + SM_TILES + OFF_B_HI;
        const uint32_t bLo = bb + SM_TILES + OFF_B_LO;

#pragma unroll
        for (int ks = 0; ks < 2; ks++) {
            // A fragments: row = mw*32 + mt*16 + (lane&15), khalf = (lane>>4)*8
            uint32_t ah[2][4], al[2][4];
            const uint32_t akoff = ks * 32 + (lane >> 4) * 16;
#pragma unroll
            for (int mt = 0; mt < 2; mt++) {
                uint32_t rowb = (mw * 32 + mt * 16 + (lane & 15)) * 64;
                uint32_t so = SWZ64(rowb + akoff);
                ldsm4(ah[mt], aHi + so);
                ldsm4(al[mt], aLo + so);
            }
            const uint32_t bkoff = ks * 32 + ((lane >> 3) & 1) * 16;
#pragma unroll
            for (int ntp = 0; ntp < 4; ntp++) {
                uint32_t rowb = (nw * 64 + ntp * 16 + ((lane >> 4) & 1) * 8 + (lane & 7)) * 64;
                uint32_t so = SWZ64(rowb + bkoff);
                uint32_t bh[4], bl[4];
                ldsm4(bh, bHi + so);
                ldsm4(bl, bLo + so);
#pragma unroll
                for (int half = 0; half < 2; half++) {
                    int nt = ntp * 2 + half;
#pragma unroll
                    for (int mt = 0; mt < 2; mt++) {
                        mma16816(acc[mt][nt], ah[mt], bh + half * 2);
                        mma16816(acc[mt][nt], ah[mt], bl + half * 2);
                        mma16816(acc[mt][nt], al[mt], bh + half * 2);
                    }
                }
            }
        }
    }
    __syncthreads();

    // ---- epilogue ----
    if (nw < 2) {
        // V warps: stash tanh as fp16
#pragma unroll
        for (int mt = 0; mt < 2; mt++)
#pragma unroll
            for (int nt = 0; nt < 8; nt++) {
                int col = nw * 64 + nt * 8 + (lane & 3) * 2;
#pragma unroll
                for (int half = 0; half < 2; half++) {
                    int row = mw * 32 + mt * 16 + half * 8 + (lane >> 2);
                    float h0 = fast_tanh(acc[mt][nt][half * 2 + 0]);
                    float h1 = fast_tanh(acc[mt][nt][half * 2 + 1]);
                    *(__half2*)(smem + SM_STASH + row * STASH_STRIDE + col * 2) =
                        __floats2half2_rn(h0, h1);
                }
            }
    }
    __syncthreads();

    float rowacc[4] = {0.f, 0.f, 0.f, 0.f};
    if (nw >= 2) {
        // U warps: gate + weight
#pragma unroll
        for (int mt = 0; mt < 2; mt++)
#pragma unroll
            for (int nt = 0; nt < 8; nt++) {
                int vcol = (nw - 2) * 64 + nt * 8 + (lane & 3) * 2;
                float w0 = ws[vcol + 0];
                float w1 = ws[vcol + 1];
#pragma unroll
                for (int half = 0; half < 2; half++) {
                    int row = mw * 32 + mt * 16 + half * 8 + (lane >> 2);
                    __half2 hh = *(const __half2*)(smem + SM_STASH +
                                                   row * STASH_STRIDE + vcol * 2);
                    float g0 = fast_sigmoid(acc[mt][nt][half * 2 + 0]);
                    float g1 = fast_sigmoid(acc[mt][nt][half * 2 + 1]);
                    rowacc[mt * 2 + half] += __low2float(hh)  * g0 * w0 +
                                             __high2float(hh) * g1 * w1;
                }
            }
    }
    __syncthreads();

    // ---- final reduction: 8 U warps -> 128 partial scores ----
    float* red = (float*)(smem + SM_RED);
    if (nw >= 2) {
#pragma unroll
        for (int ri = 0; ri < 4; ri++) {
            float p = rowacc[ri];
            p += __shfl_xor_sync(0xffffffffu, p, 1);
            p += __shfl_xor_sync(0xffffffffu, p, 2);
            if ((lane & 3) == 0) {
                int row = mw * 32 + (ri >> 1) * 16 + (ri & 1) * 8 + (lane >> 2);
                red[(nw - 2) * 128 + row] = p;
            }
        }
    }
    __syncthreads();
    if (tid < BATCH)
        g_part[(size_t)task * BATCH + tid] = red[tid] + red[128 + tid];
}

// ---------------- softmax over instance axis (sums 4 l-chunk partials) ----------------
__global__ void softmax_kernel(float* __restrict__ out)
{
    const int b   = blockIdx.x;    // 0..127
    const int tid = threadIdx.x;   // 0..255 == n
    __shared__ float sh[256];

    const float* p = g_part + ((size_t)tid * 4) * BATCH + b;
    float s = p[0] + p[BATCH] + p[2 * BATCH] + p[3 * BATCH];
    sh[tid] = s;
    __syncthreads();
#pragma unroll
    for (int off = 128; off > 0; off >>= 1) {
        if (tid < off) sh[tid] = fmaxf(sh[tid], sh[tid + off]);
        __syncthreads();
    }
    float m = sh[0];
    __syncthreads();
    float e = __expf(s - m);
    sh[tid] = e;
    __syncthreads();
#pragma unroll
    for (int off = 128; off > 0; off >>= 1) {
        if (tid < off) sh[tid] += sh[tid + off];
        __syncthreads();
    }
    out[(size_t)tid * BATCH + b] = e / sh[0];
}

extern "C" void kernel_launch(void* const* d_in, const int* in_sizes, int n_in,
                              void* d_out, int out_size)
{
    const float* x = (const float*)d_in[0];
    const float* v = (const float*)d_in[1];
    const float* u = (const float*)d_in[2];
    const float* w = (const float*)d_in[3];
    float* out = (float*)d_out;

    cudaFuncSetAttribute(mil_gemm_kernel,
                         cudaFuncAttributeMaxDynamicSharedMemorySize, SM_TOTAL);

    prep_x_kernel<<<32768, 256>>>((const float4*)x);
    prep_vu_kernel<<<2048, 256>>>(v, u);
    mil_gemm_kernel<<<1024, 512, SM_TOTAL>>>(w);
    softmax_kernel<<<BATCH, 256>>>(out);
}